// round 2
// baseline (speedup 1.0000x reference)
#include <cuda_runtime.h>

// SigKerMMD: 3 gram blocks (XX, XY, YY) of 64x64 pairs, each pair:
//   32x32 RBF gram -> 31x31 second difference -> 62x62 Goursat PDE -> corner value.
// out = (sum_XX - 2*sum_XY + sum_YY) / 4096
//
// One warp per pair. Thread t owns PDE columns 2t+1, 2t+2 (t=0..30); both columns
// and both consecutive rows share one dyadic increment, so Goursat coefficients
// (c1,c2) are precomputed per (row,col) and loaded once per 2 wavefront steps.
// The diagonal operand K[i-1][j-1] is carried as a register (inD = previous inL),
// so the hot loop has exactly ONE warp shuffle per step.

#define WARPS_PER_BLOCK 4
#define THREADS_PER_BLOCK (WARPS_PER_BLOCK * 32)
#define NPAIRS 12288          // 3 * 64 * 64
#define NBLOCKS (NPAIRS / WARPS_PER_BLOCK)   // 3072
#define SEQ 32
#define CH 5
#define SEQCH (SEQ * CH)      // 160

__device__ float g_block[NBLOCKS];

__global__ __launch_bounds__(THREADS_PER_BLOCK)
void sig_pde_kernel(const float* __restrict__ x,
                    const float* __restrict__ y,
                    const float* __restrict__ sig)
{
    __shared__ float  sh_xa[WARPS_PER_BLOCK][SEQCH];
    __shared__ float  sh_xn[WARPS_PER_BLOCK][SEQ];
    __shared__ float2 sh_c[WARPS_PER_BLOCK][31][32];   // (c1,c2) per [row][col]
    __shared__ float  sh_res[WARPS_PER_BLOCK];

    const int warp = threadIdx.x >> 5;
    const int lane = threadIdx.x & 31;
    const int w = blockIdx.x * WARPS_PER_BLOCK + warp;     // pair id 0..12287

    const int seg = w >> 12;          // 0=XX, 1=XY, 2=YY
    const int p   = w & 4095;
    const int a   = p >> 6;
    const int b   = p & 63;

    // channel scales for mu = [x0, x1*s0, x2*s1, x3*s2, x4*s3]
    float cs[CH];
    cs[0] = 1.0f;
    cs[1] = sig[0]; cs[2] = sig[1]; cs[3] = sig[2]; cs[4] = sig[3];

    const float* Aptr = ((seg < 2) ? x : y) + a * SEQCH;
    const bool   Ascale = (seg < 2);
    const float* Bptr = ((seg == 0) ? x : y) + b * SEQCH;
    const bool   Bscale = (seg == 0);

    // ---- load A sequence (possibly sigma-scaled) into shared ----
    #pragma unroll
    for (int idx = lane; idx < SEQCH; idx += 32) {
        float v = Aptr[idx];
        if (Ascale) v *= cs[idx % CH];
        sh_xa[warp][idx] = v;
    }
    __syncwarp();

    // ---- per-row squared norms of A ----
    {
        float s = 0.0f;
        #pragma unroll
        for (int c = 0; c < CH; c++) {
            float v = sh_xa[warp][lane * CH + c];
            s += v * v;
        }
        sh_xn[warp][lane] = s;
    }

    // ---- B column (lane n) into registers ----
    float yb[CH];
    float yn = 0.0f;
    #pragma unroll
    for (int c = 0; c < CH; c++) {
        float v = Bptr[lane * CH + c];
        if (Bscale) v *= cs[c];
        yb[c] = v;
        yn += v * v;
    }
    __syncwarp();

    // ---- gram column + second differences -> Goursat coefficients in shared ----
    // colDiff[m-1][n] = G[m][n]-G[m-1][n];  aa = (colDiff[i][j+1]-colDiff[i][j])/4
    // c1 = 1 + aa/2 + aa^2/12,  c2 = 1 - aa^2/12
    float gprev = 0.0f;
    #pragma unroll 4
    for (int m = 0; m < SEQ; m++) {
        float dot = 0.0f;
        #pragma unroll
        for (int c = 0; c < CH; c++)
            dot = fmaf(sh_xa[warp][m * CH + c], yb[c], dot);
        float d2 = sh_xn[warp][m] + yn - 2.0f * dot;
        float g = __expf(-d2);          // RBF_SIGMA = 1.0
        if (m > 0) {
            float cd  = g - gprev;
            float cdn = __shfl_down_sync(0xffffffffu, cd, 1);
            if (lane < 31) {
                float aa = (cdn - cd) * 0.25f;
                float a2 = aa * aa * (1.0f / 12.0f);
                sh_c[warp][m - 1][lane] =
                    make_float2(1.0f + 0.5f * aa + a2, 1.0f - a2);
            }
        }
        gprev = g;
    }
    __syncwarp();

    // ---- wavefront PDE ----
    // K is (63x63), K[0][*]=K[*][0]=1.
    // K[i][j] = (K[i][j-1]+K[i-1][j])*c1 - K[i-1][j-1]*c2
    // thread t: cols j1=2t+1, j2=2t+2; step s computes row i = s - t + 1.
    // inD (= K[i-1][2t] from neighbor) equals the PREVIOUS step's inL, carried
    // in a register -> single shuffle per step.
    float k1  = 1.0f;   // K[i][2t+1]
    float k2  = 1.0f;   // K[i][2t+2]
    float inD = 1.0f;
    float2 c  = make_float2(1.0f, 1.0f);

    #pragma unroll 2
    for (int s = 0; s < 92; s++) {
        float inL = __shfl_up_sync(0xffffffffu, k2, 1);   // K[i][2t] from t-1
        if (lane == 0) inL = 1.0f;                        // left boundary
        unsigned r = (unsigned)(s - lane);                // i-1
        if (lane < 31 && r < 62u) {
            if (!(r & 1u)) c = sh_c[warp][r >> 1][lane];  // new row-pair coeffs
            float n1 = (inL + k1) * c.x - inD * c.y;
            float n2 = (n1  + k2) * c.x - k1  * c.y;
            k1 = n1;
            k2 = n2;
        }
        inD = inL;
    }

    // lane 30 finished row 62 at step 91 -> k2 = K[62][62]
    if (lane == 30) {
        float wgt = (seg == 1) ? -2.0f : 1.0f;
        sh_res[warp] = wgt * k2;
    }
    __syncthreads();
    if (threadIdx.x == 0)
        g_block[blockIdx.x] = (sh_res[0] + sh_res[1]) + (sh_res[2] + sh_res[3]);
}

__global__ void sig_reduce_kernel(float* __restrict__ out)
{
    __shared__ float sh[256];
    const float4* p = (const float4*)g_block;   // 768 float4s
    float s = 0.0f;
    #pragma unroll
    for (int i = threadIdx.x; i < NBLOCKS / 4; i += 256) {
        float4 v = p[i];
        s += (v.x + v.y) + (v.z + v.w);
    }
    sh[threadIdx.x] = s;
    __syncthreads();
    #pragma unroll
    for (int off = 128; off > 0; off >>= 1) {
        if (threadIdx.x < off) sh[threadIdx.x] += sh[threadIdx.x + off];
        __syncthreads();
    }
    if (threadIdx.x == 0)
        out[0] = sh[0] * (1.0f / 4096.0f);
}

extern "C" void kernel_launch(void* const* d_in, const int* in_sizes, int n_in,
                              void* d_out, int out_size)
{
    // Expected order: x [64*32*5], y [64*32*5], sigma_param [4].
    // Pick sigma defensively by element count.
    const float* x = nullptr;
    const float* yy = nullptr;
    const float* sp = nullptr;
    for (int i = 0; i < n_in; i++) {
        if (in_sizes[i] == CH - 1) { sp = (const float*)d_in[i]; }
        else if (!x)               { x  = (const float*)d_in[i]; }
        else if (!yy)              { yy = (const float*)d_in[i]; }
    }

    sig_pde_kernel<<<NBLOCKS, THREADS_PER_BLOCK>>>(x, yy, sp);
    sig_reduce_kernel<<<1, 256>>>((float*)d_out);
}

// round 3
// speedup vs baseline: 1.0898x; 1.0898x over previous
#include <cuda_runtime.h>

// SigKerMMD: 3 gram blocks (XX, XY, YY) of 64x64 pairs, each pair:
//   32x32 RBF gram -> 31x31 second difference -> 62x62 Goursat PDE -> corner value.
// out = (sum_XX - 2*sum_XY + sum_YY) / 4096
//
// Single fused kernel. One warp per pair; thread t owns PDE columns 2t+1,2t+2.
// Shared memory holds only the dyadic increment aa (fp32) -> ~19KB/block ->
// ~12 blocks/SM resident (occupancy was the round-2 bottleneck theory).
// Final reduction done by the last block to finish (fixed-order, deterministic).

#define WARPS_PER_BLOCK 4
#define THREADS_PER_BLOCK (WARPS_PER_BLOCK * 32)
#define NPAIRS 12288          // 3 * 64 * 64
#define NBLOCKS (NPAIRS / WARPS_PER_BLOCK)   // 3072
#define SEQ 32
#define CH 5
#define SEQCH (SEQ * CH)      // 160

__device__ float g_block[NBLOCKS];
__device__ unsigned int g_done = 0;

__global__ __launch_bounds__(THREADS_PER_BLOCK)
void sig_pde_kernel(const float* __restrict__ x,
                    const float* __restrict__ y,
                    const float* __restrict__ sig,
                    float* __restrict__ out)
{
    __shared__ float sh_xa[WARPS_PER_BLOCK][SEQCH];
    __shared__ float sh_xn[WARPS_PER_BLOCK][SEQ];
    __shared__ float sh_aa[WARPS_PER_BLOCK][31][32];   // aa per [rowpair][colpair]
    __shared__ float sh_res[WARPS_PER_BLOCK];
    __shared__ int   sh_last;
    __shared__ float sh_red[THREADS_PER_BLOCK];

    const int warp = threadIdx.x >> 5;
    const int lane = threadIdx.x & 31;
    const int w = blockIdx.x * WARPS_PER_BLOCK + warp;     // pair id 0..12287

    const int seg = w >> 12;          // 0=XX, 1=XY, 2=YY
    const int p   = w & 4095;
    const int a   = p >> 6;
    const int b   = p & 63;

    // channel scales for mu = [x0, x1*s0, x2*s1, x3*s2, x4*s3]
    float cs[CH];
    cs[0] = 1.0f;
    cs[1] = sig[0]; cs[2] = sig[1]; cs[3] = sig[2]; cs[4] = sig[3];

    const float* Aptr = ((seg < 2) ? x : y) + a * SEQCH;
    const bool   Ascale = (seg < 2);
    const float* Bptr = ((seg == 0) ? x : y) + b * SEQCH;
    const bool   Bscale = (seg == 0);

    // ---- load A sequence (possibly sigma-scaled) into shared ----
    #pragma unroll
    for (int idx = lane; idx < SEQCH; idx += 32) {
        float v = Aptr[idx];
        if (Ascale) v *= cs[idx % CH];
        sh_xa[warp][idx] = v;
    }
    __syncwarp();

    // ---- per-row squared norms of A ----
    {
        float s = 0.0f;
        #pragma unroll
        for (int c = 0; c < CH; c++) {
            float v = sh_xa[warp][lane * CH + c];
            s += v * v;
        }
        sh_xn[warp][lane] = s;
    }

    // ---- B column (lane n) into registers ----
    float yb[CH];
    float yn = 0.0f;
    #pragma unroll
    for (int c = 0; c < CH; c++) {
        float v = Bptr[lane * CH + c];
        if (Bscale) v *= cs[c];
        yb[c] = v;
        yn += v * v;
    }
    __syncwarp();

    // ---- gram column + second differences -> aa in shared ----
    // colDiff[m-1][n] = G[m][n]-G[m-1][n];  aa = (colDiff[i][j+1]-colDiff[i][j])/4
    float gprev = 0.0f;
    #pragma unroll 4
    for (int m = 0; m < SEQ; m++) {
        float dot = 0.0f;
        #pragma unroll
        for (int c = 0; c < CH; c++)
            dot = fmaf(sh_xa[warp][m * CH + c], yb[c], dot);
        float d2 = sh_xn[warp][m] + yn - 2.0f * dot;
        float g = __expf(-d2);          // RBF_SIGMA = 1.0
        if (m > 0) {
            float cd  = g - gprev;
            float cdn = __shfl_down_sync(0xffffffffu, cd, 1);
            if (lane < 31)
                sh_aa[warp][m - 1][lane] = (cdn - cd) * 0.25f;
        }
        gprev = g;
    }
    __syncwarp();

    // ---- wavefront PDE ----
    // K is (63x63), K[0][*]=K[*][0]=1.
    // K[i][j] = (K[i][j-1]+K[i-1][j])*c1 - K[i-1][j-1]*c2
    //   c1 = 1 + aa/2 + aa^2/12,  c2 = 1 - aa^2/12, aa shared per 2x2 cell block.
    // thread t: cols j1=2t+1, j2=2t+2; step s computes row i = s - t + 1.
    // inD (= K[i-1][2t]) equals previous step's inL -> ONE shuffle per step.
    // lane 31 computes discarded garbage (nothing consumes its outputs).
    float k1  = 1.0f;   // K[i][2t+1]
    float k2  = 1.0f;   // K[i][2t+2]
    float inD = 1.0f;
    float c1 = 1.0f, c2 = 1.0f;

    #pragma unroll 2
    for (int s = 0; s < 92; s++) {
        float inL = __shfl_up_sync(0xffffffffu, k2, 1);   // K[i][2t] from t-1
        if (lane == 0) inL = 1.0f;                        // left boundary
        unsigned r = (unsigned)(s - lane);                // i-1
        if (r < 62u) {
            if (!(r & 1u)) {
                float aa = sh_aa[warp][r >> 1][lane];
                float a2 = aa * aa * (1.0f / 12.0f);
                c1 = 1.0f + 0.5f * aa + a2;
                c2 = 1.0f - a2;
            }
            float n1 = (inL + k1) * c1 - inD * c2;
            float n2 = (n1  + k2) * c1 - k1  * c2;
            k1 = n1;
            k2 = n2;
        }
        inD = inL;
    }

    // lane 30 finished row 62 at step 91 -> k2 = K[62][62]
    if (lane == 30) {
        float wgt = (seg == 1) ? -2.0f : 1.0f;
        sh_res[warp] = wgt * k2;
    }
    __syncthreads();

    // ---- publish block partial + last-block fixed-order reduction ----
    if (threadIdx.x == 0) {
        g_block[blockIdx.x] = (sh_res[0] + sh_res[1]) + (sh_res[2] + sh_res[3]);
        __threadfence();
        unsigned t = atomicAdd(&g_done, 1u);
        sh_last = (t == NBLOCKS - 1);
    }
    __syncthreads();

    if (sh_last) {
        float s = 0.0f;
        #pragma unroll
        for (int i = threadIdx.x; i < NBLOCKS; i += THREADS_PER_BLOCK)
            s += g_block[i];
        sh_red[threadIdx.x] = s;
        __syncthreads();
        #pragma unroll
        for (int off = THREADS_PER_BLOCK / 2; off > 0; off >>= 1) {
            if (threadIdx.x < off) sh_red[threadIdx.x] += sh_red[threadIdx.x + off];
            __syncthreads();
        }
        if (threadIdx.x == 0) {
            out[0] = sh_red[0] * (1.0f / 4096.0f);
            g_done = 0;   // reset for next graph replay
        }
    }
}

extern "C" void kernel_launch(void* const* d_in, const int* in_sizes, int n_in,
                              void* d_out, int out_size)
{
    // Expected order: x [64*32*5], y [64*32*5], sigma_param [4].
    // Pick sigma defensively by element count.
    const float* x = nullptr;
    const float* yy = nullptr;
    const float* sp = nullptr;
    for (int i = 0; i < n_in; i++) {
        if (in_sizes[i] == CH - 1) { sp = (const float*)d_in[i]; }
        else if (!x)               { x  = (const float*)d_in[i]; }
        else if (!yy)              { yy = (const float*)d_in[i]; }
    }

    sig_pde_kernel<<<NBLOCKS, THREADS_PER_BLOCK>>>(x, yy, sp, (float*)d_out);
}

// round 4
// speedup vs baseline: 1.1371x; 1.0434x over previous
#include <cuda_runtime.h>

// SigKerMMD: 3 gram blocks (XX, XY, YY) of 64x64 pairs, each pair:
//   32x32 RBF gram -> 31x31 second difference -> 62x62 Goursat PDE -> corner value.
// out = (sum_XX - 2*sum_XY + sum_YY) / 4096
//
// Issue-bound kernel (R3 ncu: issue=81%). This round amortizes per-step overhead:
// TWO pairs per warp, each handled by a 16-lane wavefront group; thread t owns
// PDE columns 4t+1..4t+4 (4 cells/step, 77 steps, ONE width-16 shuffle/step).
// Coefficients: one LDS.64 per row-pair via a running pointer (no per-step IMAD).

#define WARPS_PER_BLOCK 2
#define THREADS_PER_BLOCK (WARPS_PER_BLOCK * 32)
#define NPAIRS 12288                       // 3 * 64 * 64
#define PAIRS_PER_WARP 2
#define NWARPS (NPAIRS / PAIRS_PER_WARP)   // 6144
#define NBLOCKS (NWARPS / WARPS_PER_BLOCK) // 3072
#define SEQ 32
#define CH 5
#define SEQCH (SEQ * CH)                   // 160

__device__ float g_block[NBLOCKS];
__device__ unsigned int g_done = 0;

__global__ __launch_bounds__(THREADS_PER_BLOCK)
void sig_pde_kernel(const float* __restrict__ x,
                    const float* __restrict__ y,
                    const float* __restrict__ sig,
                    float* __restrict__ out)
{
    __shared__ float sh_xa[WARPS_PER_BLOCK][2][SEQCH];
    __shared__ float sh_xn[WARPS_PER_BLOCK][2][SEQ];
    __shared__ float sh_aa[WARPS_PER_BLOCK][2][31 * 32]; // [rowpair*32 + colpair]
    __shared__ float sh_res[WARPS_PER_BLOCK][2];
    __shared__ int   sh_last;
    __shared__ float sh_red[THREADS_PER_BLOCK];

    const int warp = threadIdx.x >> 5;
    const int lane = threadIdx.x & 31;
    const int wg   = blockIdx.x * WARPS_PER_BLOCK + warp;  // warp id 0..6143

    // channel scales for mu = [x0, x1*s0, x2*s1, x3*s2, x4*s3]
    float cs[CH];
    cs[0] = 1.0f;
    cs[1] = sig[0]; cs[2] = sig[1]; cs[3] = sig[2]; cs[4] = sig[3];

    // ======== Gram + dyadic increments for both pairs (full warp each) ========
    int segs[2];
    #pragma unroll 1
    for (int g = 0; g < 2; g++) {
        const int w   = wg * 2 + g;       // pair id 0..12287
        const int seg = w >> 12;          // 0=XX, 1=XY, 2=YY
        const int p   = w & 4095;
        const int a   = p >> 6;
        const int b   = p & 63;
        segs[g] = seg;

        const float* Aptr = ((seg < 2) ? x : y) + a * SEQCH;
        const bool   Ascale = (seg < 2);
        const float* Bptr = ((seg == 0) ? x : y) + b * SEQCH;
        const bool   Bscale = (seg == 0);

        // load A sequence (possibly sigma-scaled) into shared
        #pragma unroll
        for (int idx = lane; idx < SEQCH; idx += 32) {
            float v = Aptr[idx];
            if (Ascale) v *= cs[idx % CH];
            sh_xa[warp][g][idx] = v;
        }
        __syncwarp();

        // per-row squared norms of A
        {
            float s = 0.0f;
            #pragma unroll
            for (int c = 0; c < CH; c++) {
                float v = sh_xa[warp][g][lane * CH + c];
                s += v * v;
            }
            sh_xn[warp][g][lane] = s;
        }

        // B column (lane n) into registers
        float yb[CH];
        float yn = 0.0f;
        #pragma unroll
        for (int c = 0; c < CH; c++) {
            float v = Bptr[lane * CH + c];
            if (Bscale) v *= cs[c];
            yb[c] = v;
            yn += v * v;
        }
        __syncwarp();

        // gram column + second differences -> aa in shared
        // colDiff[m-1][n] = G[m][n]-G[m-1][n]; aa = (colDiff[i][j+1]-colDiff[i][j])/4
        float gprev = 0.0f;
        #pragma unroll 4
        for (int m = 0; m < SEQ; m++) {
            float dot = 0.0f;
            #pragma unroll
            for (int c = 0; c < CH; c++)
                dot = fmaf(sh_xa[warp][g][m * CH + c], yb[c], dot);
            float d2 = sh_xn[warp][g][m] + yn - 2.0f * dot;
            float gv = __expf(-d2);         // RBF_SIGMA = 1.0
            if (m > 0) {
                float cd  = gv - gprev;
                float cdn = __shfl_down_sync(0xffffffffu, cd, 1);
                // lane 31 pads colpair 31 with zero (cols 63/64 are dummies)
                float aa = (lane < 31) ? (cdn - cd) * 0.25f : 0.0f;
                sh_aa[warp][g][(m - 1) * 32 + lane] = aa;
            }
            gprev = gv;
        }
        __syncwarp();
    }

    // ======== wavefront PDE: 16-lane group per pair, 4 cols per thread ========
    // K is (63x63) per pair, K[0][*]=K[*][0]=1.
    // K[i][j] = (K[i][j-1]+K[i-1][j])*c1 - K[i-1][j-1]*c2
    //   c1 = 1 + aa/2 + aa^2/12,  c2 = 1 - aa^2/12,  aa shared per 2x2 cell block.
    // thread t owns cols 4t+1..4t+4; step s computes row i = s - t + 1.
    // inD (= K[i-1][4t]) equals previous step's inL -> ONE shuffle per step.
    const int grp = lane >> 4;       // which pair in this warp
    const int t   = lane & 15;       // wavefront thread index

    float k1 = 1.0f, k2 = 1.0f, k3 = 1.0f, k4 = 1.0f;
    float inD = 1.0f;
    float c1a = 1.0f, c2a = 1.0f, c1b = 1.0f, c2b = 1.0f;
    const float2* ap = (const float2*)(&sh_aa[warp][grp][0]) + t;

    #pragma unroll 2
    for (int s = 0; s < 77; s++) {
        float inL = __shfl_up_sync(0xffffffffu, k4, 1, 16); // K[i][4t] from t-1
        if (t == 0) inL = 1.0f;                             // left boundary
        unsigned r = (unsigned)(s - t);                     // i-1
        if (r < 62u) {
            if (!(r & 1u)) {                                // new row-pair coeffs
                float2 v = *ap; ap += 16;
                float a2x = v.x * v.x * (1.0f / 12.0f);
                c1a = 1.0f + 0.5f * v.x + a2x;
                c2a = 1.0f - a2x;
                float a2y = v.y * v.y * (1.0f / 12.0f);
                c1b = 1.0f + 0.5f * v.y + a2y;
                c2b = 1.0f - a2y;
            }
            float n1 = (inL + k1) * c1a - inD * c2a;
            float n2 = (n1  + k2) * c1a - k1  * c2a;
            float n3 = (n2  + k3) * c1b - k2  * c2b;
            float n4 = (n3  + k4) * c1b - k3  * c2b;
            k1 = n1; k2 = n2; k3 = n3; k4 = n4;
        }
        inD = inL;
    }

    // thread t=15 owns cols 61..64 -> k2 = K[62][62]
    if (t == 15) {
        float wgt = (segs[grp] == 1) ? -2.0f : 1.0f;
        sh_res[warp][grp] = wgt * k2;
    }
    __syncthreads();

    // ======== publish block partial + last-block fixed-order reduction ========
    if (threadIdx.x == 0) {
        float bsum = 0.0f;
        #pragma unroll
        for (int ww = 0; ww < WARPS_PER_BLOCK; ww++)
            bsum += sh_res[ww][0] + sh_res[ww][1];
        g_block[blockIdx.x] = bsum;
        __threadfence();
        unsigned tt = atomicAdd(&g_done, 1u);
        sh_last = (tt == NBLOCKS - 1);
    }
    __syncthreads();

    if (sh_last) {
        float s = 0.0f;
        #pragma unroll
        for (int i = threadIdx.x; i < NBLOCKS; i += THREADS_PER_BLOCK)
            s += g_block[i];
        sh_red[threadIdx.x] = s;
        __syncthreads();
        #pragma unroll
        for (int off = THREADS_PER_BLOCK / 2; off > 0; off >>= 1) {
            if (threadIdx.x < off) sh_red[threadIdx.x] += sh_red[threadIdx.x + off];
            __syncthreads();
        }
        if (threadIdx.x == 0) {
            out[0] = sh_red[0] * (1.0f / 4096.0f);
            g_done = 0;   // reset for next graph replay
        }
    }
}

extern "C" void kernel_launch(void* const* d_in, const int* in_sizes, int n_in,
                              void* d_out, int out_size)
{
    // Expected order: x [64*32*5], y [64*32*5], sigma_param [4].
    // Pick sigma defensively by element count.
    const float* x = nullptr;
    const float* yy = nullptr;
    const float* sp = nullptr;
    for (int i = 0; i < n_in; i++) {
        if (in_sizes[i] == CH - 1) { sp = (const float*)d_in[i]; }
        else if (!x)               { x  = (const float*)d_in[i]; }
        else if (!yy)              { yy = (const float*)d_in[i]; }
    }

    sig_pde_kernel<<<NBLOCKS, THREADS_PER_BLOCK>>>(x, yy, sp, (float*)d_out);
}